// round 15
// baseline (speedup 1.0000x reference)
#include <cuda_runtime.h>
#include <cuda_fp16.h>
#include <math_constants.h>
#include <stdint.h>

#define Bb  2
#define Ss  2048
#define Hh  1024
#define NHh 16
#define HDd 64
#define Mm  (Bb*Ss)    // 4096

// -------------------- scratch (device globals; no allocs allowed) ----------
__device__ __half g_Xh[Mm * Hh];
__device__ __half g_Wh[4][Hh * Hh];          // WQ, WK, WV, WO in fp16 ([K][N])
__device__ __half g_Qh[Mm * Hh];             // pre-scaled by 0.125 (exact)
__device__ __half g_Kh[Mm * Hh];
__device__ __half g_Vh[Mm * Hh];
__device__ __half g_Ch[Mm * Hh];             // attention context (fp16)

// -------------------- PTX helpers ------------------------------------------
__device__ __forceinline__ uint32_t su32(const void* p) {
    return (uint32_t)__cvta_generic_to_shared(p);
}
__device__ __forceinline__ void ldm_x4(uint32_t a, uint32_t& r0, uint32_t& r1,
                                       uint32_t& r2, uint32_t& r3) {
    asm volatile("ldmatrix.sync.aligned.m8n8.x4.shared.b16 {%0,%1,%2,%3}, [%4];"
                 : "=r"(r0), "=r"(r1), "=r"(r2), "=r"(r3) : "r"(a));
}
__device__ __forceinline__ void ldm_x4t(uint32_t a, uint32_t& r0, uint32_t& r1,
                                        uint32_t& r2, uint32_t& r3) {
    asm volatile("ldmatrix.sync.aligned.m8n8.x4.trans.shared.b16 {%0,%1,%2,%3}, [%4];"
                 : "=r"(r0), "=r"(r1), "=r"(r2), "=r"(r3) : "r"(a));
}
__device__ __forceinline__ void mma16816(float* c, const uint32_t* a, const uint32_t* b) {
    asm volatile(
        "mma.sync.aligned.m16n8k16.row.col.f32.f16.f16.f32 "
        "{%0,%1,%2,%3}, {%4,%5,%6,%7}, {%8,%9}, {%0,%1,%2,%3};"
        : "+f"(c[0]), "+f"(c[1]), "+f"(c[2]), "+f"(c[3])
        : "r"(a[0]), "r"(a[1]), "r"(a[2]), "r"(a[3]), "r"(b[0]), "r"(b[1]));
}
#define CPA16(dst, src) asm volatile("cp.async.cg.shared.global [%0], [%1], 16;" :: "r"(dst), "l"(src))
#define CPCOMMIT()      asm volatile("cp.async.commit_group;")
#define CPWAIT0()       asm volatile("cp.async.wait_group 0;")
#define CPWAIT1()       asm volatile("cp.async.wait_group 1;")

__device__ __forceinline__ uint32_t packh2(float a, float b) {
    __half2 h = __floats2half2_rn(a, b);   // .x = a (low = k even elem)
    return *(uint32_t*)&h;
}

// -------------------- fp32 -> fp16 converts --------------------------------
__global__ __launch_bounds__(256) void f2h(const float* __restrict__ s,
                                           __half* __restrict__ d) {
    int i = (blockIdx.x * 256 + threadIdx.x) * 4;
    float4 v = *(const float4*)(s + i);
    __half2* dp = (__half2*)(d + i);
    dp[0] = __floats2half2_rn(v.x, v.y);
    dp[1] = __floats2half2_rn(v.z, v.w);
}
// all four weights in one launch (grid.y = weight index)
__global__ __launch_bounds__(256)
void f2hw(const float* __restrict__ W0, const float* __restrict__ W1,
          const float* __restrict__ W2, const float* __restrict__ W3,
          __half* __restrict__ d) {
    const int z = blockIdx.y;
    const float* s = (z == 0) ? W0 : (z == 1) ? W1 : (z == 2) ? W2 : W3;
    int i = (blockIdx.x * 256 + threadIdx.x) * 4;
    float4 v = *(const float4*)(s + i);
    __half2* dp = (__half2*)(d + (size_t)z * Hh * Hh + i);
    dp[0] = __floats2half2_rn(v.x, v.y);
    dp[1] = __floats2half2_rn(v.z, v.w);
}

// -------------------- fp16 tensor-core GEMM, 3-stage pipeline (proven) -----
#define GSTAGE_H 9472
#define GSMEM_B  (3 * GSTAGE_H * 2)   // 56832 bytes

template <bool OUTH, bool SCALE>
__global__ __launch_bounds__(256, 2)
void gemm_h(const __half* __restrict__ A, const __half* __restrict__ Bw,
            float* __restrict__ Cf, __half* __restrict__ Chh)
{
    extern __shared__ __align__(16) __half sm[];

    const int tid = threadIdx.x, lane = tid & 31, warp = tid >> 5;
    const int wm = warp >> 2, wn = warp & 3;
    const int rowBase = blockIdx.y * 128, colBase = blockIdx.x * 128;

    const int arow = tid >> 2, acq = tid & 3;   // A: rows arow, arow+64
    const int bnq  = tid & 15, bkr = tid >> 4;  // B: k-rows bkr, bkr+16

    float acc[4][4][4];
#pragma unroll
    for (int i = 0; i < 4; i++)
#pragma unroll
        for (int j = 0; j < 4; j++)
#pragma unroll
            for (int k = 0; k < 4; k++) acc[i][j][k] = 0.f;

    auto load_tile = [&](int t, int s) {
        __half* As = sm + s * GSTAGE_H;
        __half* Bs = sm + s * GSTAGE_H + 5120;
        const __half* Ag = A + (size_t)(rowBase + arow) * Hh + t * 32 + acq * 8;
        CPA16(su32(As + arow * 40 + acq * 8), Ag);
        CPA16(su32(As + (arow + 64) * 40 + acq * 8), Ag + (size_t)64 * Hh);
        const __half* Bg = Bw + (size_t)(t * 32 + bkr) * Hh + colBase + bnq * 8;
        CPA16(su32(Bs + bkr * 136 + bnq * 8), Bg);
        CPA16(su32(Bs + (bkr + 16) * 136 + bnq * 8), Bg + (size_t)16 * Hh);
    };

    load_tile(0, 0); CPCOMMIT();
    load_tile(1, 1); CPCOMMIT();

    for (int t = 0; t < 32; t++) {
        const int st = t - (t / 3) * 3;          // t % 3
        CPWAIT1();
        __syncthreads();
        if (t + 2 < 32) load_tile(t + 2, (t + 2) - ((t + 2) / 3) * 3);
        CPCOMMIT();

        const __half* As = sm + st * GSTAGE_H;
        const __half* Bs = sm + st * GSTAGE_H + 5120;
#pragma unroll
        for (int ks = 0; ks < 2; ks++) {
            uint32_t a[4][4], b[4][2];
#pragma unroll
            for (int mf = 0; mf < 4; mf++)
                ldm_x4(su32(As + (wm * 64 + mf * 16 + (lane & 15)) * 40
                               + ks * 16 + ((lane >> 4) << 3)),
                       a[mf][0], a[mf][1], a[mf][2], a[mf][3]);
            const int m = lane >> 3;
#pragma unroll
            for (int g = 0; g < 2; g++) {
                uint32_t addr = su32(Bs + (ks * 16 + ((m & 1) << 3) + (lane & 7)) * 136
                                       + wn * 32 + g * 16 + ((m >> 1) << 3));
                ldm_x4t(addr, b[2 * g][0], b[2 * g][1], b[2 * g + 1][0], b[2 * g + 1][1]);
            }
#pragma unroll
            for (int mf = 0; mf < 4; mf++)
#pragma unroll
                for (int nf = 0; nf < 4; nf++)
                    mma16816(acc[mf][nf], a[mf], b[nf]);
        }
    }

#pragma unroll
    for (int mf = 0; mf < 4; mf++) {
        const int r0 = rowBase + wm * 64 + mf * 16 + (lane >> 2);
#pragma unroll
        for (int nf = 0; nf < 4; nf++) {
            float c0 = acc[mf][nf][0], c1 = acc[mf][nf][1];
            float c2 = acc[mf][nf][2], c3 = acc[mf][nf][3];
            if (SCALE) { c0 *= 0.125f; c1 *= 0.125f; c2 *= 0.125f; c3 *= 0.125f; }
            const int c = colBase + wn * 32 + nf * 8 + ((lane & 3) << 1);
            if (OUTH) {
                *(__half2*)&Chh[(size_t)r0 * Hh + c]       = __floats2half2_rn(c0, c1);
                *(__half2*)&Chh[(size_t)(r0 + 8) * Hh + c] = __floats2half2_rn(c2, c3);
            } else {
                *(float2*)&Cf[(size_t)r0 * Hh + c]       = make_float2(c0, c1);
                *(float2*)&Cf[(size_t)(r0 + 8) * Hh + c] = make_float2(c2, c3);
            }
        }
    }
}

// -------------------- fp16 flash attention, q-tile 128 ---------------------
// CTA: 128 q-rows x (head,batch); 256 thr = 8 warps x 16 q-rows. Per-warp
// code identical to the proven 64-row version; K/V tiles now amortized over
// 2x q-rows (half the global+smem traffic per flop). Q staged through
// Ks[1]/Vs[1] and register-resident before the mainloop reuses them.
__global__ __launch_bounds__(256, 2)
void attn_h(const __half* __restrict__ Qh, const __half* __restrict__ Kh,
            const __half* __restrict__ Vh, const int* __restrict__ mask,
            __half* __restrict__ Ch)
{
    __shared__ __align__(16) __half Ks[2][64][72];
    __shared__ __align__(16) __half Vs[2][64][72];
    __shared__ float Ms[2][64];

    const int tid = threadIdx.x, lane = tid & 31, warp = tid >> 5;
    const int qt = blockIdx.x, h = blockIdx.y, b = blockIdx.z;
    const int qbase = qt * 128;

    const __half* Qg = Qh + (size_t)(b * Ss + qbase) * Hh + h * HDd;
    const __half* Kg = Kh + (size_t)(b * Ss) * Hh + h * HDd;
    const __half* Vg = Vh + (size_t)(b * Ss) * Hh + h * HDd;
    const int* mrw = mask + b * Ss;

    const int lrow = tid >> 3, lcq = tid & 7;    // 32 rows x 8 col-groups

    // stage Q (128 rows) into Ks[1] (rows 0-63) and Vs[1] (rows 64-127)
#pragma unroll
    for (int i = 0; i < 4; i++) {
        const int r = lrow + 32 * i;
        uint4 v = *(const uint4*)(Qg + (size_t)r * Hh + lcq * 8);
        if (r < 64) *(uint4*)&Ks[1][r][lcq * 8] = v;
        else        *(uint4*)&Vs[1][r - 64][lcq * 8] = v;
    }

    // prologue: async K/V tile 0 -> buf 0 + mask tile 0
#pragma unroll
    for (int i = 0; i < 2; i++) {
        const int r = lrow + 32 * i;
        CPA16(su32(&Ks[0][r][lcq * 8]), Kg + (size_t)r * Hh + lcq * 8);
        CPA16(su32(&Vs[0][r][lcq * 8]), Vg + (size_t)r * Hh + lcq * 8);
    }
    CPCOMMIT();
    if (tid < 64) Ms[0][tid] = (mrw[tid] == 0) ? -CUDART_INF_F : 0.f;
    __syncthreads();                       // Q staged & visible

    // Q fragments: warps 0-3 from Ks[1], warps 4-7 from Vs[1]
    uint32_t qa[4][4];
    {
        const int qrow = (warp & 3) * 16 + (lane & 15);
        const __half* qsrc = (warp < 4) ? &Ks[1][0][0] : &Vs[1][0][0];
#pragma unroll
        for (int kf = 0; kf < 4; kf++)
            ldm_x4(su32(qsrc + qrow * 72 + kf * 16 + ((lane >> 4) << 3)),
                   qa[kf][0], qa[kf][1], qa[kf][2], qa[kf][3]);
    }
    CPWAIT0();
    __syncthreads();                       // Ks[1]/Vs[1] free + tile0 landed

    float o[8][4];
#pragma unroll
    for (int i = 0; i < 8; i++)
#pragma unroll
        for (int j = 0; j < 4; j++) o[i][j] = 0.f;
    float mprev[2] = {-1e30f, -1e30f};
    float lsum[2]  = {0.f, 0.f};

    for (int kt = 0; kt < Ss / 64; kt++) {
        const int buf = kt & 1;
        if (kt < Ss / 64 - 1) {
            const __half* Kg2 = Kg + (size_t)((kt + 1) * 64) * Hh;
            const __half* Vg2 = Vg + (size_t)((kt + 1) * 64) * Hh;
#pragma unroll
            for (int i = 0; i < 2; i++) {
                const int r = lrow + 32 * i;
                CPA16(su32(&Ks[buf ^ 1][r][lcq * 8]), Kg2 + (size_t)r * Hh + lcq * 8);
                CPA16(su32(&Vs[buf ^ 1][r][lcq * 8]), Vg2 + (size_t)r * Hh + lcq * 8);
            }
            CPCOMMIT();
            if (tid < 64)
                Ms[buf ^ 1][tid] = (mrw[(kt + 1) * 64 + tid] == 0) ? -CUDART_INF_F : 0.f;
        }

        // ---- S = Q @ K^T (Q pre-scaled) ----
        float s[8][4];
#pragma unroll
        for (int i = 0; i < 8; i++)
#pragma unroll
            for (int j = 0; j < 4; j++) s[i][j] = 0.f;

        const int m = lane >> 3;
#pragma unroll
        for (int kf = 0; kf < 4; kf++) {
            uint32_t kb[8][2];
#pragma unroll
            for (int g = 0; g < 4; g++) {
                uint32_t addr = su32(&Ks[buf][g * 16 + ((m >> 1) << 3) + (lane & 7)]
                                             [kf * 16 + ((m & 1) << 3)]);
                ldm_x4(addr, kb[2 * g][0], kb[2 * g][1], kb[2 * g + 1][0], kb[2 * g + 1][1]);
            }
#pragma unroll
            for (int nf = 0; nf < 8; nf++)
                mma16816(s[nf], qa[kf], kb[nf]);
        }

        // ---- clip, mask, online softmax ----
        float es[2];
#pragma unroll
        for (int r = 0; r < 2; r++) {
            float mx = -CUDART_INF_F;
#pragma unroll
            for (int nf = 0; nf < 8; nf++) {
                const int c0 = nf * 8 + ((lane & 3) << 1);
                float v0 = fminf(fmaxf(s[nf][2 * r],     -10000.f), 10000.f) + Ms[buf][c0];
                float v1 = fminf(fmaxf(s[nf][2 * r + 1], -10000.f), 10000.f) + Ms[buf][c0 + 1];
                s[nf][2 * r] = v0; s[nf][2 * r + 1] = v1;
                mx = fmaxf(mx, fmaxf(v0, v1));
            }
            mx = fmaxf(mx, __shfl_xor_sync(0xffffffffu, mx, 1));
            mx = fmaxf(mx, __shfl_xor_sync(0xffffffffu, mx, 2));
            const float mn = fmaxf(mprev[r], mx);
            es[r] = __expf(mprev[r] - mn);
            mprev[r] = mn;
            float sum = 0.f;
#pragma unroll
            for (int nf = 0; nf < 8; nf++) {
                float p0 = __expf(s[nf][2 * r]     - mn);
                float p1 = __expf(s[nf][2 * r + 1] - mn);
                s[nf][2 * r] = p0; s[nf][2 * r + 1] = p1;
                sum += p0 + p1;
            }
            sum += __shfl_xor_sync(0xffffffffu, sum, 1);
            sum += __shfl_xor_sync(0xffffffffu, sum, 2);
            lsum[r] = lsum[r] * es[r] + sum;
        }
#pragma unroll
        for (int nf = 0; nf < 8; nf++) {
            o[nf][0] *= es[0]; o[nf][1] *= es[0];
            o[nf][2] *= es[1]; o[nf][3] *= es[1];
        }

        // ---- O += P @ V ----
#pragma unroll
        for (int j = 0; j < 4; j++) {
            uint32_t pa[4];
            pa[0] = packh2(s[2 * j][0],     s[2 * j][1]);
            pa[1] = packh2(s[2 * j][2],     s[2 * j][3]);
            pa[2] = packh2(s[2 * j + 1][0], s[2 * j + 1][1]);
            pa[3] = packh2(s[2 * j + 1][2], s[2 * j + 1][3]);
#pragma unroll
            for (int g = 0; g < 4; g++) {
                uint32_t vb[4];
                uint32_t addr = su32(&Vs[buf][j * 16 + ((m & 1) << 3) + (lane & 7)]
                                             [g * 16 + ((m >> 1) << 3)]);
                ldm_x4t(addr, vb[0], vb[1], vb[2], vb[3]);
                mma16816(o[2 * g],     pa, &vb[0]);
                mma16816(o[2 * g + 1], pa, &vb[2]);
            }
        }
        CPWAIT0();
        __syncthreads();
    }

    const float i0 = 1.f / lsum[0];
    const float i1 = 1.f / lsum[1];
    const int r0 = qbase + warp * 16 + (lane >> 2);
#pragma unroll
    for (int nf = 0; nf < 8; nf++) {
        const int c = h * HDd + nf * 8 + ((lane & 3) << 1);
        *(__half2*)&Ch[(size_t)(b * Ss + r0) * Hh + c] =
            __floats2half2_rn(o[nf][0] * i0, o[nf][1] * i0);
        *(__half2*)&Ch[(size_t)(b * Ss + r0 + 8) * Hh + c] =
            __floats2half2_rn(o[nf][2] * i1, o[nf][3] * i1);
    }
}

// ---------------------------------------------------------------------------
extern "C" void kernel_launch(void* const* d_in, const int* in_sizes, int n_in,
                              void* d_out, int out_size)
{
    const float* X    = (const float*)d_in[0];
    const int*   mask = (const int*)  d_in[1];
    const float* WQ   = (const float*)d_in[2];
    const float* WK   = (const float*)d_in[3];
    const float* WV   = (const float*)d_in[4];
    const float* WO   = (const float*)d_in[5];
    float* out = (float*)d_out;

    __half *pXh, *pWh, *pQh, *pKh, *pVh, *pCh;
    cudaGetSymbolAddress((void**)&pXh, g_Xh);
    cudaGetSymbolAddress((void**)&pWh, g_Wh);
    cudaGetSymbolAddress((void**)&pQh, g_Qh);
    cudaGetSymbolAddress((void**)&pKh, g_Kh);
    cudaGetSymbolAddress((void**)&pVh, g_Vh);
    cudaGetSymbolAddress((void**)&pCh, g_Ch);

    cudaFuncSetAttribute(gemm_h<true , true >, cudaFuncAttributeMaxDynamicSharedMemorySize, GSMEM_B);
    cudaFuncSetAttribute(gemm_h<true , false>, cudaFuncAttributeMaxDynamicSharedMemorySize, GSMEM_B);
    cudaFuncSetAttribute(gemm_h<false, false>, cudaFuncAttributeMaxDynamicSharedMemorySize, GSMEM_B);

    f2h<<<(Mm * Hh) / 1024, 256>>>(X, pXh);
    f2hw<<<dim3((Hh * Hh) / 1024, 4), 256>>>(WQ, WK, WV, WO, pWh);

    dim3 gg(Hh / 128, Mm / 128);   // (8, 32)
    gemm_h<true, true ><<<gg, 256, GSMEM_B>>>(pXh, pWh + 0 * (size_t)Hh * Hh, nullptr, pQh);
    gemm_h<true, false><<<gg, 256, GSMEM_B>>>(pXh, pWh + 1 * (size_t)Hh * Hh, nullptr, pKh);
    gemm_h<true, false><<<gg, 256, GSMEM_B>>>(pXh, pWh + 2 * (size_t)Hh * Hh, nullptr, pVh);

    attn_h<<<dim3(Ss / 128, NHh, Bb), 256>>>(pQh, pKh, pVh, mask, pCh);

    gemm_h<false, false><<<gg, 256, GSMEM_B>>>(pCh, pWh + 3 * (size_t)Hh * Hh, out, nullptr);

    (void)in_sizes; (void)n_in; (void)out_size;
}

// round 16
// speedup vs baseline: 1.0674x; 1.0674x over previous
#include <cuda_runtime.h>
#include <cuda_fp16.h>
#include <math_constants.h>
#include <stdint.h>

#define Bb  2
#define Ss  2048
#define Hh  1024
#define NHh 16
#define HDd 64
#define Mm  (Bb*Ss)    // 4096

// Q pre-scale: 0.125 * log2(e) -> softmax runs in the exp2 domain.
#define QSCALE 0.1803368801111204f
// clip bound in log2 domain: 10000 * log2(e)
#define CLIP2  14426.950408889634f

// -------------------- scratch (device globals; no allocs allowed) ----------
__device__ __half g_Xh[Mm * Hh];
__device__ __half g_Wh[4][Hh * Hh];          // WQ, WK, WV, WO in fp16 ([K][N])
__device__ __half g_Qh[Mm * Hh];             // pre-scaled by 0.125*log2e
__device__ __half g_Kh[Mm * Hh];
__device__ __half g_Vh[Mm * Hh];
__device__ __half g_Ch[Mm * Hh];             // attention context (fp16)

// -------------------- PTX helpers ------------------------------------------
__device__ __forceinline__ uint32_t su32(const void* p) {
    return (uint32_t)__cvta_generic_to_shared(p);
}
__device__ __forceinline__ void ldm_x4(uint32_t a, uint32_t& r0, uint32_t& r1,
                                       uint32_t& r2, uint32_t& r3) {
    asm volatile("ldmatrix.sync.aligned.m8n8.x4.shared.b16 {%0,%1,%2,%3}, [%4];"
                 : "=r"(r0), "=r"(r1), "=r"(r2), "=r"(r3) : "r"(a));
}
__device__ __forceinline__ void ldm_x4t(uint32_t a, uint32_t& r0, uint32_t& r1,
                                        uint32_t& r2, uint32_t& r3) {
    asm volatile("ldmatrix.sync.aligned.m8n8.x4.trans.shared.b16 {%0,%1,%2,%3}, [%4];"
                 : "=r"(r0), "=r"(r1), "=r"(r2), "=r"(r3) : "r"(a));
}
__device__ __forceinline__ void mma16816(float* c, const uint32_t* a, const uint32_t* b) {
    asm volatile(
        "mma.sync.aligned.m16n8k16.row.col.f32.f16.f16.f32 "
        "{%0,%1,%2,%3}, {%4,%5,%6,%7}, {%8,%9}, {%0,%1,%2,%3};"
        : "+f"(c[0]), "+f"(c[1]), "+f"(c[2]), "+f"(c[3])
        : "r"(a[0]), "r"(a[1]), "r"(a[2]), "r"(a[3]), "r"(b[0]), "r"(b[1]));
}
#define CPA16(dst, src) asm volatile("cp.async.cg.shared.global [%0], [%1], 16;" :: "r"(dst), "l"(src))
#define CPCOMMIT()      asm volatile("cp.async.commit_group;")
#define CPWAIT0()       asm volatile("cp.async.wait_group 0;")
#define CPWAIT1()       asm volatile("cp.async.wait_group 1;")

__device__ __forceinline__ uint32_t packh2(float a, float b) {
    __half2 h = __floats2half2_rn(a, b);   // .x = a (low = k even elem)
    return *(uint32_t*)&h;
}

// -------------------- fp32 -> fp16 converts --------------------------------
__global__ __launch_bounds__(256) void f2h(const float* __restrict__ s,
                                           __half* __restrict__ d) {
    int i = (blockIdx.x * 256 + threadIdx.x) * 4;
    float4 v = *(const float4*)(s + i);
    __half2* dp = (__half2*)(d + i);
    dp[0] = __floats2half2_rn(v.x, v.y);
    dp[1] = __floats2half2_rn(v.z, v.w);
}
// all four weights in one launch (grid.y = weight index)
__global__ __launch_bounds__(256)
void f2hw(const float* __restrict__ W0, const float* __restrict__ W1,
          const float* __restrict__ W2, const float* __restrict__ W3,
          __half* __restrict__ d) {
    const int z = blockIdx.y;
    const float* s = (z == 0) ? W0 : (z == 1) ? W1 : (z == 2) ? W2 : W3;
    int i = (blockIdx.x * 256 + threadIdx.x) * 4;
    float4 v = *(const float4*)(s + i);
    __half2* dp = (__half2*)(d + (size_t)z * Hh * Hh + i);
    dp[0] = __floats2half2_rn(v.x, v.y);
    dp[1] = __floats2half2_rn(v.z, v.w);
}

// -------------------- fp16 tensor-core GEMM, 3-stage pipeline (proven) -----
#define GSTAGE_H 9472
#define GSMEM_B  (3 * GSTAGE_H * 2)   // 56832 bytes

template <bool OUTH, bool SCALE>
__global__ __launch_bounds__(256, 2)
void gemm_h(const __half* __restrict__ A, const __half* __restrict__ Bw,
            float* __restrict__ Cf, __half* __restrict__ Chh)
{
    extern __shared__ __align__(16) __half sm[];

    const int tid = threadIdx.x, lane = tid & 31, warp = tid >> 5;
    const int wm = warp >> 2, wn = warp & 3;
    const int rowBase = blockIdx.y * 128, colBase = blockIdx.x * 128;

    const int arow = tid >> 2, acq = tid & 3;   // A: rows arow, arow+64
    const int bnq  = tid & 15, bkr = tid >> 4;  // B: k-rows bkr, bkr+16

    float acc[4][4][4];
#pragma unroll
    for (int i = 0; i < 4; i++)
#pragma unroll
        for (int j = 0; j < 4; j++)
#pragma unroll
            for (int k = 0; k < 4; k++) acc[i][j][k] = 0.f;

    auto load_tile = [&](int t, int s) {
        __half* As = sm + s * GSTAGE_H;
        __half* Bs = sm + s * GSTAGE_H + 5120;
        const __half* Ag = A + (size_t)(rowBase + arow) * Hh + t * 32 + acq * 8;
        CPA16(su32(As + arow * 40 + acq * 8), Ag);
        CPA16(su32(As + (arow + 64) * 40 + acq * 8), Ag + (size_t)64 * Hh);
        const __half* Bg = Bw + (size_t)(t * 32 + bkr) * Hh + colBase + bnq * 8;
        CPA16(su32(Bs + bkr * 136 + bnq * 8), Bg);
        CPA16(su32(Bs + (bkr + 16) * 136 + bnq * 8), Bg + (size_t)16 * Hh);
    };

    load_tile(0, 0); CPCOMMIT();
    load_tile(1, 1); CPCOMMIT();

    for (int t = 0; t < 32; t++) {
        const int st = t - (t / 3) * 3;          // t % 3
        CPWAIT1();
        __syncthreads();
        if (t + 2 < 32) load_tile(t + 2, (t + 2) - ((t + 2) / 3) * 3);
        CPCOMMIT();

        const __half* As = sm + st * GSTAGE_H;
        const __half* Bs = sm + st * GSTAGE_H + 5120;
#pragma unroll
        for (int ks = 0; ks < 2; ks++) {
            uint32_t a[4][4], b[4][2];
#pragma unroll
            for (int mf = 0; mf < 4; mf++)
                ldm_x4(su32(As + (wm * 64 + mf * 16 + (lane & 15)) * 40
                               + ks * 16 + ((lane >> 4) << 3)),
                       a[mf][0], a[mf][1], a[mf][2], a[mf][3]);
            const int m = lane >> 3;
#pragma unroll
            for (int g = 0; g < 2; g++) {
                uint32_t addr = su32(Bs + (ks * 16 + ((m & 1) << 3) + (lane & 7)) * 136
                                       + wn * 32 + g * 16 + ((m >> 1) << 3));
                ldm_x4t(addr, b[2 * g][0], b[2 * g][1], b[2 * g + 1][0], b[2 * g + 1][1]);
            }
#pragma unroll
            for (int mf = 0; mf < 4; mf++)
#pragma unroll
                for (int nf = 0; nf < 4; nf++)
                    mma16816(acc[mf][nf], a[mf], b[nf]);
        }
    }

#pragma unroll
    for (int mf = 0; mf < 4; mf++) {
        const int r0 = rowBase + wm * 64 + mf * 16 + (lane >> 2);
#pragma unroll
        for (int nf = 0; nf < 4; nf++) {
            float c0 = acc[mf][nf][0], c1 = acc[mf][nf][1];
            float c2 = acc[mf][nf][2], c3 = acc[mf][nf][3];
            if (SCALE) { c0 *= QSCALE; c1 *= QSCALE; c2 *= QSCALE; c3 *= QSCALE; }
            const int c = colBase + wn * 32 + nf * 8 + ((lane & 3) << 1);
            if (OUTH) {
                *(__half2*)&Chh[(size_t)r0 * Hh + c]       = __floats2half2_rn(c0, c1);
                *(__half2*)&Chh[(size_t)(r0 + 8) * Hh + c] = __floats2half2_rn(c2, c3);
            } else {
                *(float2*)&Cf[(size_t)r0 * Hh + c]       = make_float2(c0, c1);
                *(float2*)&Cf[(size_t)(r0 + 8) * Hh + c] = make_float2(c2, c3);
            }
        }
    }
}

// -------------------- fp16 flash attention (round-14 proven shape) ---------
// Q pre-scaled by 0.125*log2e -> scores are already in the exp2 domain:
// softmax uses bare exp2f (MUFU only, no FMUL). Clip bound scaled to match.
__global__ __launch_bounds__(128, 4)
void attn_h(const __half* __restrict__ Qh, const __half* __restrict__ Kh,
            const __half* __restrict__ Vh, const int* __restrict__ mask,
            __half* __restrict__ Ch)
{
    __shared__ __align__(16) __half Ks[2][64][72];
    __shared__ __align__(16) __half Vs[2][64][72];
    __shared__ float Ms[2][64];

    const int tid = threadIdx.x, lane = tid & 31, warp = tid >> 5;
    const int qt = blockIdx.x, h = blockIdx.y, b = blockIdx.z;
    const int qbase = qt * 64;

    const __half* Qg = Qh + (size_t)(b * Ss + qbase) * Hh + h * HDd;
    const __half* Kg = Kh + (size_t)(b * Ss) * Hh + h * HDd;
    const __half* Vg = Vh + (size_t)(b * Ss) * Hh + h * HDd;
    const int* mrw = mask + b * Ss;

    const int lrow = tid >> 3, lcq = tid & 7;

#pragma unroll
    for (int i = 0; i < 4; i++)
        *(uint4*)&Ks[1][lrow + 16 * i][lcq * 8] =
            *(const uint4*)(Qg + (size_t)(lrow + 16 * i) * Hh + lcq * 8);

#pragma unroll
    for (int i = 0; i < 4; i++) {
        CPA16(su32(&Ks[0][lrow + 16 * i][lcq * 8]),
              Kg + (size_t)(lrow + 16 * i) * Hh + lcq * 8);
        CPA16(su32(&Vs[0][lrow + 16 * i][lcq * 8]),
              Vg + (size_t)(lrow + 16 * i) * Hh + lcq * 8);
    }
    CPCOMMIT();
    if (tid < 64) Ms[0][tid] = (mrw[tid] == 0) ? -CUDART_INF_F : 0.f;
    __syncthreads();

    uint32_t qa[4][4];
#pragma unroll
    for (int kf = 0; kf < 4; kf++)
        ldm_x4(su32(&Ks[1][warp * 16 + (lane & 15)][kf * 16 + ((lane >> 4) << 3)]),
               qa[kf][0], qa[kf][1], qa[kf][2], qa[kf][3]);
    CPWAIT0();
    __syncthreads();

    float o[8][4];
#pragma unroll
    for (int i = 0; i < 8; i++)
#pragma unroll
        for (int j = 0; j < 4; j++) o[i][j] = 0.f;
    float mprev[2] = {-1e30f, -1e30f};
    float lsum[2]  = {0.f, 0.f};

    for (int kt = 0; kt < Ss / 64; kt++) {
        const int buf = kt & 1;
        if (kt < Ss / 64 - 1) {
            const __half* Kg2 = Kg + (size_t)((kt + 1) * 64) * Hh;
            const __half* Vg2 = Vg + (size_t)((kt + 1) * 64) * Hh;
#pragma unroll
            for (int i = 0; i < 4; i++) {
                CPA16(su32(&Ks[buf ^ 1][lrow + 16 * i][lcq * 8]),
                      Kg2 + (size_t)(lrow + 16 * i) * Hh + lcq * 8);
                CPA16(su32(&Vs[buf ^ 1][lrow + 16 * i][lcq * 8]),
                      Vg2 + (size_t)(lrow + 16 * i) * Hh + lcq * 8);
            }
            CPCOMMIT();
            if (tid < 64)
                Ms[buf ^ 1][tid] = (mrw[(kt + 1) * 64 + tid] == 0) ? -CUDART_INF_F : 0.f;
        }

        // ---- S = Q @ K^T (log2-domain scores) ----
        float s[8][4];
#pragma unroll
        for (int i = 0; i < 8; i++)
#pragma unroll
            for (int j = 0; j < 4; j++) s[i][j] = 0.f;

        const int m = lane >> 3;
#pragma unroll
        for (int kf = 0; kf < 4; kf++) {
            uint32_t kb[8][2];
#pragma unroll
            for (int g = 0; g < 4; g++) {
                uint32_t addr = su32(&Ks[buf][g * 16 + ((m >> 1) << 3) + (lane & 7)]
                                             [kf * 16 + ((m & 1) << 3)]);
                ldm_x4(addr, kb[2 * g][0], kb[2 * g][1], kb[2 * g + 1][0], kb[2 * g + 1][1]);
            }
#pragma unroll
            for (int nf = 0; nf < 8; nf++)
                mma16816(s[nf], qa[kf], kb[nf]);
        }

        // ---- clip, mask, online softmax (exp2 domain) ----
        float es[2];
#pragma unroll
        for (int r = 0; r < 2; r++) {
            float mx = -CUDART_INF_F;
#pragma unroll
            for (int nf = 0; nf < 8; nf++) {
                const int c0 = nf * 8 + ((lane & 3) << 1);
                float v0 = fminf(fmaxf(s[nf][2 * r],     -CLIP2), CLIP2) + Ms[buf][c0];
                float v1 = fminf(fmaxf(s[nf][2 * r + 1], -CLIP2), CLIP2) + Ms[buf][c0 + 1];
                s[nf][2 * r] = v0; s[nf][2 * r + 1] = v1;
                mx = fmaxf(mx, fmaxf(v0, v1));
            }
            mx = fmaxf(mx, __shfl_xor_sync(0xffffffffu, mx, 1));
            mx = fmaxf(mx, __shfl_xor_sync(0xffffffffu, mx, 2));
            const float mn = fmaxf(mprev[r], mx);
            es[r] = exp2f(mprev[r] - mn);
            mprev[r] = mn;
            float sum = 0.f;
#pragma unroll
            for (int nf = 0; nf < 8; nf++) {
                float p0 = exp2f(s[nf][2 * r]     - mn);
                float p1 = exp2f(s[nf][2 * r + 1] - mn);
                s[nf][2 * r] = p0; s[nf][2 * r + 1] = p1;
                sum += p0 + p1;
            }
            sum += __shfl_xor_sync(0xffffffffu, sum, 1);
            sum += __shfl_xor_sync(0xffffffffu, sum, 2);
            lsum[r] = lsum[r] * es[r] + sum;
        }
#pragma unroll
        for (int nf = 0; nf < 8; nf++) {
            o[nf][0] *= es[0]; o[nf][1] *= es[0];
            o[nf][2] *= es[1]; o[nf][3] *= es[1];
        }

        // ---- O += P @ V ----
#pragma unroll
        for (int j = 0; j < 4; j++) {
            uint32_t pa[4];
            pa[0] = packh2(s[2 * j][0],     s[2 * j][1]);
            pa[1] = packh2(s[2 * j][2],     s[2 * j][3]);
            pa[2] = packh2(s[2 * j + 1][0], s[2 * j + 1][1]);
            pa[3] = packh2(s[2 * j + 1][2], s[2 * j + 1][3]);
#pragma unroll
            for (int g = 0; g < 4; g++) {
                uint32_t vb[4];
                uint32_t addr = su32(&Vs[buf][j * 16 + ((m & 1) << 3) + (lane & 7)]
                                             [g * 16 + ((m >> 1) << 3)]);
                ldm_x4t(addr, vb[0], vb[1], vb[2], vb[3]);
                mma16816(o[2 * g],     pa, &vb[0]);
                mma16816(o[2 * g + 1], pa, &vb[2]);
            }
        }
        CPWAIT0();
        __syncthreads();
    }

    const float i0 = 1.f / lsum[0];
    const float i1 = 1.f / lsum[1];
    const int r0 = qbase + warp * 16 + (lane >> 2);
#pragma unroll
    for (int nf = 0; nf < 8; nf++) {
        const int c = h * HDd + nf * 8 + ((lane & 3) << 1);
        *(__half2*)&Ch[(size_t)(b * Ss + r0) * Hh + c] =
            __floats2half2_rn(o[nf][0] * i0, o[nf][1] * i0);
        *(__half2*)&Ch[(size_t)(b * Ss + r0 + 8) * Hh + c] =
            __floats2half2_rn(o[nf][2] * i1, o[nf][3] * i1);
    }
}

// ---------------------------------------------------------------------------
extern "C" void kernel_launch(void* const* d_in, const int* in_sizes, int n_in,
                              void* d_out, int out_size)
{
    const float* X    = (const float*)d_in[0];
    const int*   mask = (const int*)  d_in[1];
    const float* WQ   = (const float*)d_in[2];
    const float* WK   = (const float*)d_in[3];
    const float* WV   = (const float*)d_in[4];
    const float* WO   = (const float*)d_in[5];
    float* out = (float*)d_out;

    __half *pXh, *pWh, *pQh, *pKh, *pVh, *pCh;
    cudaGetSymbolAddress((void**)&pXh, g_Xh);
    cudaGetSymbolAddress((void**)&pWh, g_Wh);
    cudaGetSymbolAddress((void**)&pQh, g_Qh);
    cudaGetSymbolAddress((void**)&pKh, g_Kh);
    cudaGetSymbolAddress((void**)&pVh, g_Vh);
    cudaGetSymbolAddress((void**)&pCh, g_Ch);

    cudaFuncSetAttribute(gemm_h<true , true >, cudaFuncAttributeMaxDynamicSharedMemorySize, GSMEM_B);
    cudaFuncSetAttribute(gemm_h<true , false>, cudaFuncAttributeMaxDynamicSharedMemorySize, GSMEM_B);
    cudaFuncSetAttribute(gemm_h<false, false>, cudaFuncAttributeMaxDynamicSharedMemorySize, GSMEM_B);

    f2h<<<(Mm * Hh) / 1024, 256>>>(X, pXh);
    f2hw<<<dim3((Hh * Hh) / 1024, 4), 256>>>(WQ, WK, WV, WO, pWh);

    dim3 gg(Hh / 128, Mm / 128);   // (8, 32)
    gemm_h<true, true ><<<gg, 256, GSMEM_B>>>(pXh, pWh + 0 * (size_t)Hh * Hh, nullptr, pQh);
    gemm_h<true, false><<<gg, 256, GSMEM_B>>>(pXh, pWh + 1 * (size_t)Hh * Hh, nullptr, pKh);
    gemm_h<true, false><<<gg, 256, GSMEM_B>>>(pXh, pWh + 2 * (size_t)Hh * Hh, nullptr, pVh);

    attn_h<<<dim3(Ss / 64, NHh, Bb), 128>>>(pQh, pKh, pVh, mask, pCh);

    gemm_h<false, false><<<gg, 256, GSMEM_B>>>(pCh, pWh + 3 * (size_t)Hh * Hh, out, nullptr);

    (void)in_sizes; (void)n_in; (void)out_size;
}